// round 1
// baseline (speedup 1.0000x reference)
#include <cuda_runtime.h>
#include <cuda_bf16.h>
#include <math.h>

#define B_   32
#define S_   64
#define T_   48
#define TD   47            // T-1 decode steps
#define V_   32000
#define E_   512
#define H_   1024
#define H3_  3072
#define KSPLIT 4

// ---------------- device scratch (no allocations allowed) ----------------
__device__ float g_emb  [B_*S_*E_];        // gathered encoder embeddings
__device__ float g_gi0  [B_*S_*H3_];       // encoder layer0 input gates (all t)
__device__ float g_enc  [B_*S_*H_];        // encoder outputs
__device__ float g_proj [B_*S_*H_];        // attn projection of enc outputs
__device__ float g_h0   [B_*H_];           // layer0 hidden (enc then dec)
__device__ float g_h1   [B_*H_];           // layer1 hidden (enc then dec)
__device__ float g_gip  [KSPLIT*B_*H3_];   // split-K partials (input gates)
__device__ float g_ghp  [KSPLIT*B_*H3_];   // split-K partials (hidden gates)
__device__ float g_score[B_*S_];
__device__ float g_x    [B_*(E_+H_)];      // decoder step input [emb, ctx]
__device__ float g_cat  [TD*B_*2*H_];      // [d1, ctx] rows for final GEMM

// ---------------- init: gather embeddings, zero hidden states ----------------
__global__ void k_init(const int* __restrict__ src_ids, const float* __restrict__ enc_emb)
{
    int idx = blockIdx.x * blockDim.x + threadIdx.x;
    if (idx < B_*S_*E_) {
        int m = idx / E_;
        int k = idx - m * E_;
        g_emb[idx] = enc_emb[(size_t)src_ids[m] * E_ + k];
    }
    if (idx < B_*H_) { g_h0[idx] = 0.f; g_h1[idx] = 0.f; }
}

// ---------------- big GEMM: C[M,N] = A[M,K] @ W[N,K]^T (+bias) ----------------
// mode 0: row-major store C[m*N+n]
// mode 1: scatter store to output tensor (B, TD, V) with m = t*B + b
__global__ __launch_bounds__(256)
void k_gemm128(const float* __restrict__ A, const float* __restrict__ W,
               const float* __restrict__ bias, float* __restrict__ C,
               int M, int N, int K, int mode)
{
    __shared__ float As[8][128];
    __shared__ float Bs[8][128];
    int tid = threadIdx.x;
    int n0 = blockIdx.x * 128;
    int m0 = blockIdx.y * 128;
    int tx = tid & 15, ty = tid >> 4;
    int lrow = tid >> 1, lpart = (tid & 1) * 4;

    float acc[8][8];
#pragma unroll
    for (int i = 0; i < 8; i++)
#pragma unroll
        for (int j = 0; j < 8; j++) acc[i][j] = 0.f;

    for (int kk = 0; kk < K; kk += 8) {
        float4 av = make_float4(0.f, 0.f, 0.f, 0.f);
        if (m0 + lrow < M)
            av = *(const float4*)(A + (size_t)(m0 + lrow) * K + kk + lpart);
        As[lpart + 0][lrow] = av.x; As[lpart + 1][lrow] = av.y;
        As[lpart + 2][lrow] = av.z; As[lpart + 3][lrow] = av.w;

        float4 bv = *(const float4*)(W + (size_t)(n0 + lrow) * K + kk + lpart);
        Bs[lpart + 0][lrow] = bv.x; Bs[lpart + 1][lrow] = bv.y;
        Bs[lpart + 2][lrow] = bv.z; Bs[lpart + 3][lrow] = bv.w;
        __syncthreads();

#pragma unroll
        for (int k = 0; k < 8; k++) {
            float4 a0 = *(const float4*)&As[k][ty * 8];
            float4 a1 = *(const float4*)&As[k][ty * 8 + 4];
            float4 b0 = *(const float4*)&Bs[k][tx * 8];
            float4 b1 = *(const float4*)&Bs[k][tx * 8 + 4];
            float a[8] = {a0.x, a0.y, a0.z, a0.w, a1.x, a1.y, a1.z, a1.w};
            float b[8] = {b0.x, b0.y, b0.z, b0.w, b1.x, b1.y, b1.z, b1.w};
#pragma unroll
            for (int i = 0; i < 8; i++)
#pragma unroll
                for (int j = 0; j < 8; j++) acc[i][j] += a[i] * b[j];
        }
        __syncthreads();
    }

#pragma unroll
    for (int i = 0; i < 8; i++) {
        int m = m0 + ty * 8 + i;
        if (m >= M) continue;
#pragma unroll
        for (int j = 0; j < 8; j++) {
            int n = n0 + tx * 8 + j;
            float v = acc[i][j] + (bias ? bias[n] : 0.f);
            if (mode == 0) {
                C[(size_t)m * N + n] = v;
            } else {
                int b = m & (B_ - 1);
                int t = m >> 5;
                C[(size_t)b * TD * V_ + (size_t)t * V_ + n] = v;
            }
        }
    }
}

// ---------------- skinny recurrent GEMM: partial C_p[32,N] over K/KSPLIT ----------------
// grid: (N/64, KSPLIT, nz).  z picks operand set (two independent GEMMs per launch).
__global__ __launch_bounds__(256)
void k_gemm_small(const float* A0, const float* W0, float* C0, int K0,
                  const float* A1, const float* W1, float* C1, int K1, int N)
{
    const float* A; const float* W; float* C; int K;
    if (blockIdx.z == 0) { A = A0; W = W0; C = C0; K = K0; }
    else                 { A = A1; W = W1; C = C1; K = K1; }

    int n0 = blockIdx.x * 64;
    int p  = blockIdx.y;
    int klen = K / KSPLIT;
    int kbeg = p * klen;
    float* Cp = C + (size_t)p * B_ * N;

    __shared__ float As[32][32];      // [m][k]  (broadcast reads)
    __shared__ float Ws[64][33];      // [n][k]  padded (2-way reads)

    int tid  = threadIdx.x;           // 256
    int tcol = tid & 31;              // c0 = tcol*2
    int trow = tid >> 5;              // r0 = trow*4
    int r0 = trow * 4, c0 = tcol * 2;

    float acc00 = 0.f, acc01 = 0.f, acc10 = 0.f, acc11 = 0.f;
    float acc20 = 0.f, acc21 = 0.f, acc30 = 0.f, acc31 = 0.f;

    for (int kk = kbeg; kk < kbeg + klen; kk += 32) {
#pragma unroll
        for (int i = 0; i < 4; i++) {
            int l = tid + i * 256;
            int m = l >> 5, k = l & 31;
            As[m][k] = A[(size_t)m * K + kk + k];
        }
#pragma unroll
        for (int i = 0; i < 8; i++) {
            int l = tid + i * 256;
            int n = l >> 5, k = l & 31;
            Ws[n][k] = W[(size_t)(n0 + n) * K + kk + k];
        }
        __syncthreads();
#pragma unroll
        for (int k = 0; k < 32; k++) {
            float a0 = As[r0 + 0][k];
            float a1 = As[r0 + 1][k];
            float a2 = As[r0 + 2][k];
            float a3 = As[r0 + 3][k];
            float b0 = Ws[c0 + 0][k];
            float b1 = Ws[c0 + 1][k];
            acc00 += a0 * b0; acc01 += a0 * b1;
            acc10 += a1 * b0; acc11 += a1 * b1;
            acc20 += a2 * b0; acc21 += a2 * b1;
            acc30 += a3 * b0; acc31 += a3 * b1;
        }
        __syncthreads();
    }

    Cp[(size_t)(r0 + 0) * N + n0 + c0]     = acc00;
    Cp[(size_t)(r0 + 0) * N + n0 + c0 + 1] = acc01;
    Cp[(size_t)(r0 + 1) * N + n0 + c0]     = acc10;
    Cp[(size_t)(r0 + 1) * N + n0 + c0 + 1] = acc11;
    Cp[(size_t)(r0 + 2) * N + n0 + c0]     = acc20;
    Cp[(size_t)(r0 + 2) * N + n0 + c0 + 1] = acc21;
    Cp[(size_t)(r0 + 3) * N + n0 + c0]     = acc30;
    Cp[(size_t)(r0 + 3) * N + n0 + c0 + 1] = acc31;
}

// ---------------- GRU gate combine (also sums split-K partials) ----------------
__global__ __launch_bounds__(256)
void k_combine(const float* __restrict__ gi, int gi_stride, int gi_parts,
               const float* __restrict__ bias_i,
               const float* __restrict__ gh, int gh_parts,
               const float* __restrict__ bias_h,
               const float* __restrict__ hprev, float* __restrict__ hout,
               float* __restrict__ extra, int extra_stride)
{
    int idx = blockIdx.x * 256 + threadIdx.x;   // B_*H_ threads
    int b = idx >> 10;
    int j = idx & (H_ - 1);

    float gr = 0.f, gz = 0.f, gn = 0.f;
    for (int p = 0; p < gi_parts; p++) {
        const float* g = gi + (size_t)p * B_ * H3_ + (size_t)b * gi_stride;
        gr += g[j]; gz += g[H_ + j]; gn += g[2 * H_ + j];
    }
    if (bias_i) { gr += bias_i[j]; gz += bias_i[H_ + j]; gn += bias_i[2 * H_ + j]; }

    float hr = 0.f, hz = 0.f, hn = 0.f;
    for (int p = 0; p < gh_parts; p++) {
        const float* g = gh + (size_t)p * B_ * H3_ + (size_t)b * H3_;
        hr += g[j]; hz += g[H_ + j]; hn += g[2 * H_ + j];
    }
    hr += bias_h[j]; hz += bias_h[H_ + j]; hn += bias_h[2 * H_ + j];

    float r = 1.f / (1.f + expf(-(gr + hr)));
    float z = 1.f / (1.f + expf(-(gz + hz)));
    float n = tanhf(gn + r * hn);
    float h = (1.f - z) * n + z * hprev[idx];
    hout[idx] = h;
    if (extra) extra[(size_t)b * extra_stride + j] = h;
}

// ---------------- attention scores: score[b,s] = proj[b,s,:] . d1[b,:] (masked) ----------------
__global__ __launch_bounds__(256)
void k_score(const float* __restrict__ d1, const int* __restrict__ src_ids)
{
    int gt = blockIdx.x * blockDim.x + threadIdx.x;
    int w = gt >> 5;
    int lane = gt & 31;
    if (w >= B_ * S_) return;
    int b = w >> 6;
    const float* pr = g_proj + (size_t)w * H_;
    const float* hv = d1 + (size_t)b * H_;
    float acc = 0.f;
#pragma unroll 4
    for (int k = lane; k < H_; k += 32) acc += pr[k] * hv[k];
#pragma unroll
    for (int o = 16; o; o >>= 1) acc += __shfl_xor_sync(0xffffffffu, acc, o);
    if (lane == 0)
        g_score[w] = (src_ids[w] != 0) ? acc : -1e9f;
}

// ---------------- softmax + context + build decoder input + stash ctx into cat ----------------
__global__ __launch_bounds__(256)
void k_softctx(const float* __restrict__ dec_emb, const int* __restrict__ tgt_ids, int t)
{
    int b = blockIdx.x;
    int tid = threadIdx.x;
    __shared__ float sc[S_];
    __shared__ float ev[S_];

    if (tid < S_) sc[tid] = g_score[b * S_ + tid];
    __syncthreads();

    float mx = -1e30f;
#pragma unroll
    for (int s = 0; s < S_; s++) mx = fmaxf(mx, sc[s]);
    if (tid < S_) ev[tid] = expf(sc[tid] - mx);
    __syncthreads();

    float sum = 0.f;
#pragma unroll
    for (int s = 0; s < S_; s++) sum += ev[s];
    float inv = 1.f / sum;

    for (int h = tid; h < H_; h += 256) {
        float acc = 0.f;
#pragma unroll
        for (int s = 0; s < S_; s++)
            acc += ev[s] * g_enc[((size_t)b * S_ + s) * H_ + h];
        acc *= inv;
        g_x[b * (E_ + H_) + E_ + h] = acc;
        g_cat[((size_t)t * B_ + b) * (2 * H_) + H_ + h] = acc;
    }

    int tok = tgt_ids[b * T_ + t];
    for (int i = tid; i < E_; i += 256)
        g_x[b * (E_ + H_) + i] = dec_emb[(size_t)tok * E_ + i];
}

// ---------------- host ----------------
extern "C" void kernel_launch(void* const* d_in, const int* in_sizes, int n_in,
                              void* d_out, int out_size)
{
    const int*   src_ids  = (const int*)d_in[0];
    const int*   tgt_ids  = (const int*)d_in[2];
    const float* enc_emb  = (const float*)d_in[3];
    const float* dec_emb  = (const float*)d_in[4];
    const float* enc_wih0 = (const float*)d_in[5];
    const float* enc_whh0 = (const float*)d_in[6];
    const float* enc_bih0 = (const float*)d_in[7];
    const float* enc_bhh0 = (const float*)d_in[8];
    const float* enc_wih1 = (const float*)d_in[9];
    const float* enc_whh1 = (const float*)d_in[10];
    const float* enc_bih1 = (const float*)d_in[11];
    const float* enc_bhh1 = (const float*)d_in[12];
    const float* dec_wih0 = (const float*)d_in[13];
    const float* dec_whh0 = (const float*)d_in[14];
    const float* dec_bih0 = (const float*)d_in[15];
    const float* dec_bhh0 = (const float*)d_in[16];
    const float* dec_wih1 = (const float*)d_in[17];
    const float* dec_whh1 = (const float*)d_in[18];
    const float* dec_bih1 = (const float*)d_in[19];
    const float* dec_bhh1 = (const float*)d_in[20];
    const float* attn_w   = (const float*)d_in[21];
    const float* out_w    = (const float*)d_in[22];
    const float* out_b    = (const float*)d_in[23];
    float* out = (float*)d_out;

    float *emb, *gi0, *enc, *h0, *h1, *gip, *ghp, *x, *cat;
    cudaGetSymbolAddress((void**)&emb, g_emb);
    cudaGetSymbolAddress((void**)&gi0, g_gi0);
    cudaGetSymbolAddress((void**)&enc, g_enc);
    cudaGetSymbolAddress((void**)&h0,  g_h0);
    cudaGetSymbolAddress((void**)&h1,  g_h1);
    cudaGetSymbolAddress((void**)&gip, g_gip);
    cudaGetSymbolAddress((void**)&ghp, g_ghp);
    cudaGetSymbolAddress((void**)&x,   g_x);
    cudaGetSymbolAddress((void**)&cat, g_cat);
    float *proj;
    cudaGetSymbolAddress((void**)&proj, g_proj);

    // 1) gather src embeddings + zero hidden states
    k_init<<<(B_*S_*E_ + 255) / 256, 256>>>(src_ids, enc_emb);

    // 2) batched encoder layer-0 input gates: gi0 = emb @ wih0^T + bih0
    k_gemm128<<<dim3(H3_ / 128, (B_*S_) / 128), 256>>>(
        emb, enc_wih0, enc_bih0, gi0, B_*S_, H3_, E_, 0);

    // 3) encoder recurrence
    for (int t = 0; t < S_; t++) {
        k_gemm_small<<<dim3(H3_ / 64, KSPLIT, 1), 256>>>(
            h0, enc_whh0, ghp, H_, nullptr, nullptr, nullptr, 0, H3_);
        k_combine<<<(B_*H_) / 256, 256>>>(
            gi0 + (size_t)t * H3_, S_ * H3_, 1, nullptr,
            ghp, KSPLIT, enc_bhh0, h0, h0, nullptr, 0);
        k_gemm_small<<<dim3(H3_ / 64, KSPLIT, 2), 256>>>(
            h0, enc_wih1, gip, H_, h1, enc_whh1, ghp, H_, H3_);
        k_combine<<<(B_*H_) / 256, 256>>>(
            gip, H3_, KSPLIT, enc_bih1,
            ghp, KSPLIT, enc_bhh1, h1, h1, enc + (size_t)t * H_, S_ * H_);
    }

    // 4) attention projection: proj = enc_out @ attn_w^T
    k_gemm128<<<dim3(H_ / 128, (B_*S_) / 128), 256>>>(
        enc, attn_w, nullptr, proj, B_*S_, H_, H_, 0);

    // 5) decoder (h0/h1 carry over as d0/d1); logits deferred to one big GEMM
    for (int t = 0; t < TD; t++) {
        k_score<<<(B_*S_*32) / 256, 256>>>(h1, src_ids);
        k_softctx<<<B_, 256>>>(dec_emb, tgt_ids, t);
        k_gemm_small<<<dim3(H3_ / 64, KSPLIT, 2), 256>>>(
            x, dec_wih0, gip, E_ + H_, h0, dec_whh0, ghp, H_, H3_);
        k_combine<<<(B_*H_) / 256, 256>>>(
            gip, H3_, KSPLIT, dec_bih0,
            ghp, KSPLIT, dec_bhh0, h0, h0, nullptr, 0);
        k_gemm_small<<<dim3(H3_ / 64, KSPLIT, 2), 256>>>(
            h0, dec_wih1, gip, H_, h1, dec_whh1, ghp, H_, H3_);
        k_combine<<<(B_*H_) / 256, 256>>>(
            gip, H3_, KSPLIT, dec_bih1,
            ghp, KSPLIT, dec_bhh1, h1, h1,
            cat + (size_t)t * B_ * 2 * H_, 2 * H_);
    }

    // 6) one big output projection: logits = cat @ out_w^T + out_b, scattered to (B,TD,V)
    k_gemm128<<<dim3(V_ / 128, (TD * B_ + 127) / 128), 256>>>(
        cat, out_w, out_b, out, TD * B_, V_, 2 * H_, 1);
}

// round 2
// speedup vs baseline: 1.3261x; 1.3261x over previous
#include <cuda_runtime.h>
#include <math.h>
#include <stdint.h>

#define B_   32
#define S_   64
#define T_   48
#define TD   47
#define V_   32000
#define E_   512
#define H_   1024
#define H3_  3072
#define KSPLIT 4

// ---------------- device scratch ----------------
__device__ float g_emb  [B_*S_*E_];
__device__ float g_demb [TD*B_*E_];
__device__ float g_gi0  [B_*S_*H3_];
__device__ float g_giemb[TD*B_*H3_];
__device__ float g_enc  [B_*S_*H_];
__device__ float g_proj [B_*S_*H_];
__device__ float g_h0   [B_*H_];
__device__ float g_h1   [B_*H_];
__device__ float g_gip  [KSPLIT*B_*H3_];
__device__ float g_ghp  [KSPLIT*B_*H3_];
__device__ float g_x    [B_*H_];           // decoder step context
__device__ float g_cat  [TD*B_*2*H_];      // [d1, ctx] rows for final GEMM

// ---------------- init: gather encoder embeddings, zero hidden ----------------
__global__ void k_init(const int* __restrict__ src_ids, const float* __restrict__ enc_emb)
{
    int idx = blockIdx.x * blockDim.x + threadIdx.x;
    if (idx < B_*S_*E_) {
        int m = idx >> 9;
        int k = idx & 511;
        g_emb[idx] = enc_emb[(size_t)src_ids[m] * E_ + k];
    }
    if (idx < B_*H_) { g_h0[idx] = 0.f; g_h1[idx] = 0.f; }
}

// ---------------- gather decoder embeddings, rows m = t*B + b ----------------
__global__ void k_demb(const int* __restrict__ tgt_ids, const float* __restrict__ dec_emb)
{
    int idx = blockIdx.x * blockDim.x + threadIdx.x;
    if (idx >= TD*B_*E_) return;
    int m = idx >> 9;
    int k = idx & 511;
    int b = m & 31, t = m >> 5;
    g_demb[idx] = dec_emb[(size_t)tgt_ids[b*T_ + t] * E_ + k];
}

// ---------------- fp32 tiled GEMM: C[M,N] = A[M,K] @ W[N,:]^T (ld=ldw) + bias ----------------
__global__ __launch_bounds__(256)
void k_gemm128(const float* __restrict__ A, const float* __restrict__ W, int ldw,
               const float* __restrict__ bias, float* __restrict__ C,
               int M, int N, int K)
{
    __shared__ float As[8][128];
    __shared__ float Bs[8][128];
    int tid = threadIdx.x;
    int n0 = blockIdx.x * 128;
    int m0 = blockIdx.y * 128;
    int tx = tid & 15, ty = tid >> 4;
    int lrow = tid >> 1, lpart = (tid & 1) * 4;

    float acc[8][8];
#pragma unroll
    for (int i = 0; i < 8; i++)
#pragma unroll
        for (int j = 0; j < 8; j++) acc[i][j] = 0.f;

    for (int kk = 0; kk < K; kk += 8) {
        float4 av = make_float4(0.f, 0.f, 0.f, 0.f);
        if (m0 + lrow < M)
            av = *(const float4*)(A + (size_t)(m0 + lrow) * K + kk + lpart);
        As[lpart + 0][lrow] = av.x; As[lpart + 1][lrow] = av.y;
        As[lpart + 2][lrow] = av.z; As[lpart + 3][lrow] = av.w;

        float4 bv = *(const float4*)(W + (size_t)(n0 + lrow) * ldw + kk + lpart);
        Bs[lpart + 0][lrow] = bv.x; Bs[lpart + 1][lrow] = bv.y;
        Bs[lpart + 2][lrow] = bv.z; Bs[lpart + 3][lrow] = bv.w;
        __syncthreads();

#pragma unroll
        for (int k = 0; k < 8; k++) {
            float4 a0 = *(const float4*)&As[k][ty * 8];
            float4 a1 = *(const float4*)&As[k][ty * 8 + 4];
            float4 b0 = *(const float4*)&Bs[k][tx * 8];
            float4 b1 = *(const float4*)&Bs[k][tx * 8 + 4];
            float a[8] = {a0.x, a0.y, a0.z, a0.w, a1.x, a1.y, a1.z, a1.w};
            float b[8] = {b0.x, b0.y, b0.z, b0.w, b1.x, b1.y, b1.z, b1.w};
#pragma unroll
            for (int i = 0; i < 8; i++)
#pragma unroll
                for (int j = 0; j < 8; j++) acc[i][j] += a[i] * b[j];
        }
        __syncthreads();
    }

#pragma unroll
    for (int i = 0; i < 8; i++) {
        int m = m0 + ty * 8 + i;
        if (m >= M) continue;
#pragma unroll
        for (int j = 0; j < 8; j++) {
            int n = n0 + tx * 8 + j;
            C[(size_t)m * N + n] = acc[i][j] + (bias ? bias[n] : 0.f);
        }
    }
}

// ---------------- tf32 tensor-core GEMM for output projection ----------------
// C scatter: row m = t*B+b -> out[b*TD*V + t*V + n].  A clamped-row loads for M tail.
__global__ __launch_bounds__(256, 2)
void k_gemm_tc(const float* __restrict__ A, const float* __restrict__ W,
               const float* __restrict__ bias, float* __restrict__ C,
               int M, int N, int K)
{
    __shared__ float As[2][128*20];
    __shared__ float Bs[2][128*20];
    const int tid = threadIdx.x;
    const int m0 = blockIdx.x * 128;
    const int n0 = blockIdx.y * 128;
    const int warp = tid >> 5, lane = tid & 31;
    const int g = lane >> 2, tg = lane & 3;
    const int wm = (warp >> 2) * 64, wn = (warp & 3) * 32;

    const int lrow = tid >> 2;         // 0..63
    const int lk   = (tid & 3) * 4;    // 0,4,8,12
    int ar0 = m0 + lrow;      if (ar0 >= M) ar0 = M - 1;
    int ar1 = m0 + lrow + 64; if (ar1 >= M) ar1 = M - 1;
    const float* ag0 = A + (size_t)ar0 * K + lk;
    const float* ag1 = A + (size_t)ar1 * K + lk;
    const float* bg0 = W + (size_t)(n0 + lrow) * K + lk;
    const float* bg1 = W + (size_t)(n0 + lrow + 64) * K + lk;
    uint32_t sa0 = (uint32_t)__cvta_generic_to_shared(&As[0][lrow*20 + lk]);
    uint32_t sa1 = (uint32_t)__cvta_generic_to_shared(&As[0][(lrow+64)*20 + lk]);
    uint32_t sb0 = (uint32_t)__cvta_generic_to_shared(&Bs[0][lrow*20 + lk]);
    uint32_t sb1 = (uint32_t)__cvta_generic_to_shared(&Bs[0][(lrow+64)*20 + lk]);
    const uint32_t ssz = 128*20*4;

    float acc[4][4][4];
#pragma unroll
    for (int i = 0; i < 4; i++)
#pragma unroll
        for (int j = 0; j < 4; j++)
#pragma unroll
            for (int q = 0; q < 4; q++) acc[i][j][q] = 0.f;

    auto issue = [&](int st, int c) {
        uint32_t so = st ? ssz : 0;
        const float* p0 = ag0 + c*16;
        const float* p1 = ag1 + c*16;
        const float* p2 = bg0 + c*16;
        const float* p3 = bg1 + c*16;
        asm volatile("cp.async.cg.shared.global [%0], [%1], 16;\n" :: "r"(sa0+so), "l"(p0));
        asm volatile("cp.async.cg.shared.global [%0], [%1], 16;\n" :: "r"(sa1+so), "l"(p1));
        asm volatile("cp.async.cg.shared.global [%0], [%1], 16;\n" :: "r"(sb0+so), "l"(p2));
        asm volatile("cp.async.cg.shared.global [%0], [%1], 16;\n" :: "r"(sb1+so), "l"(p3));
    };

    const int nchunk = K / 16;
    issue(0, 0);
    asm volatile("cp.async.commit_group;\n");

    for (int c = 0; c < nchunk; c++) {
        if (c + 1 < nchunk) issue((c + 1) & 1, c + 1);
        asm volatile("cp.async.commit_group;\n");
        asm volatile("cp.async.wait_group 1;\n");
        __syncthreads();
        const float* as = As[c & 1];
        const float* bs = Bs[c & 1];
#pragma unroll
        for (int ks = 0; ks < 16; ks += 8) {
            uint32_t af[4][4], bf[4][2];
#pragma unroll
            for (int i = 0; i < 4; i++) {
                int r = wm + i*16 + g;
                float f0 = as[r*20 + ks + tg];
                float f1 = as[(r+8)*20 + ks + tg];
                float f2 = as[r*20 + ks + tg + 4];
                float f3 = as[(r+8)*20 + ks + tg + 4];
                asm("cvt.rna.tf32.f32 %0, %1;" : "=r"(af[i][0]) : "f"(f0));
                asm("cvt.rna.tf32.f32 %0, %1;" : "=r"(af[i][1]) : "f"(f1));
                asm("cvt.rna.tf32.f32 %0, %1;" : "=r"(af[i][2]) : "f"(f2));
                asm("cvt.rna.tf32.f32 %0, %1;" : "=r"(af[i][3]) : "f"(f3));
            }
#pragma unroll
            for (int j = 0; j < 4; j++) {
                int cc = wn + j*8 + g;
                float f0 = bs[cc*20 + ks + tg];
                float f1 = bs[cc*20 + ks + tg + 4];
                asm("cvt.rna.tf32.f32 %0, %1;" : "=r"(bf[j][0]) : "f"(f0));
                asm("cvt.rna.tf32.f32 %0, %1;" : "=r"(bf[j][1]) : "f"(f1));
            }
#pragma unroll
            for (int i = 0; i < 4; i++)
#pragma unroll
                for (int j = 0; j < 4; j++) {
                    asm volatile(
                        "mma.sync.aligned.m16n8k8.row.col.f32.tf32.tf32.f32 "
                        "{%0,%1,%2,%3}, {%4,%5,%6,%7}, {%8,%9}, {%0,%1,%2,%3};\n"
                        : "+f"(acc[i][j][0]), "+f"(acc[i][j][1]),
                          "+f"(acc[i][j][2]), "+f"(acc[i][j][3])
                        : "r"(af[i][0]), "r"(af[i][1]), "r"(af[i][2]), "r"(af[i][3]),
                          "r"(bf[j][0]), "r"(bf[j][1]));
                }
        }
        __syncthreads();
    }

#pragma unroll
    for (int i = 0; i < 4; i++) {
#pragma unroll
        for (int j = 0; j < 4; j++) {
            int n = n0 + wn + j*8 + 2*tg;
            float bv0 = bias[n], bv1 = bias[n + 1];
            int m = m0 + wm + i*16 + g;
            if (m < M) {
                int bb = m & (B_ - 1), tt = m >> 5;
                float* o = C + (size_t)bb*TD*V_ + (size_t)tt*V_ + n;
                o[0] = acc[i][j][0] + bv0;
                o[1] = acc[i][j][1] + bv1;
            }
            int m2 = m + 8;
            if (m2 < M) {
                int bb = m2 & (B_ - 1), tt = m2 >> 5;
                float* o = C + (size_t)bb*TD*V_ + (size_t)tt*V_ + n;
                o[0] = acc[i][j][2] + bv0;
                o[1] = acc[i][j][3] + bv1;
            }
        }
    }
}

// ---------------- skinny recurrent GEMM: split-K partials, 2 operand sets ----------------
__global__ __launch_bounds__(256)
void k_gemm_small(const float* A0, const float* W0, int ldw0, float* C0, int K0,
                  const float* A1, const float* W1, int ldw1, float* C1, int K1, int N)
{
    const float* A; const float* W; float* C; int K, ldw;
    if (blockIdx.z == 0) { A = A0; W = W0; C = C0; K = K0; ldw = ldw0; }
    else                 { A = A1; W = W1; C = C1; K = K1; ldw = ldw1; }

    int n0 = blockIdx.x * 64;
    int p  = blockIdx.y;
    int klen = K / KSPLIT;
    int kbeg = p * klen;
    float* Cp = C + (size_t)p * B_ * N;

    __shared__ float As[32][32];
    __shared__ float Ws[64][33];

    int tid  = threadIdx.x;
    int tcol = tid & 31;
    int trow = tid >> 5;
    int r0 = trow * 4, c0 = tcol * 2;

    float acc00 = 0.f, acc01 = 0.f, acc10 = 0.f, acc11 = 0.f;
    float acc20 = 0.f, acc21 = 0.f, acc30 = 0.f, acc31 = 0.f;

    for (int kk = kbeg; kk < kbeg + klen; kk += 32) {
#pragma unroll
        for (int i = 0; i < 4; i++) {
            int l = tid + i * 256;
            int m = l >> 5, k = l & 31;
            As[m][k] = A[(size_t)m * K + kk + k];
        }
#pragma unroll
        for (int i = 0; i < 8; i++) {
            int l = tid + i * 256;
            int n = l >> 5, k = l & 31;
            Ws[n][k] = W[(size_t)(n0 + n) * ldw + kk + k];
        }
        __syncthreads();
#pragma unroll
        for (int k = 0; k < 32; k++) {
            float a0 = As[r0 + 0][k];
            float a1 = As[r0 + 1][k];
            float a2 = As[r0 + 2][k];
            float a3 = As[r0 + 3][k];
            float b0 = Ws[c0 + 0][k];
            float b1 = Ws[c0 + 1][k];
            acc00 += a0 * b0; acc01 += a0 * b1;
            acc10 += a1 * b0; acc11 += a1 * b1;
            acc20 += a2 * b0; acc21 += a2 * b1;
            acc30 += a3 * b0; acc31 += a3 * b1;
        }
        __syncthreads();
    }

    Cp[(size_t)(r0 + 0) * N + n0 + c0]     = acc00;
    Cp[(size_t)(r0 + 0) * N + n0 + c0 + 1] = acc01;
    Cp[(size_t)(r0 + 1) * N + n0 + c0]     = acc10;
    Cp[(size_t)(r0 + 1) * N + n0 + c0 + 1] = acc11;
    Cp[(size_t)(r0 + 2) * N + n0 + c0]     = acc20;
    Cp[(size_t)(r0 + 2) * N + n0 + c0 + 1] = acc21;
    Cp[(size_t)(r0 + 3) * N + n0 + c0]     = acc30;
    Cp[(size_t)(r0 + 3) * N + n0 + c0 + 1] = acc31;
}

// ---------------- GRU gate combine, compile-time unrolled partial sums ----------------
template<int GIP, int GHP, bool PRE>
__global__ __launch_bounds__(256)
void k_combine_t(const float* __restrict__ gi, int gi_stride,
                 const float* __restrict__ bias_i,
                 const float* __restrict__ gpre,
                 const float* __restrict__ gh,
                 const float* __restrict__ bias_h,
                 const float* __restrict__ hprev,
                 float* __restrict__ hout,
                 float* __restrict__ extra, int extra_stride)
{
    int idx = blockIdx.x * 256 + threadIdx.x;
    int b = idx >> 10;
    int j = idx & (H_ - 1);

    float gr = 0.f, gz = 0.f, gn = 0.f;
#pragma unroll
    for (int p = 0; p < GIP; p++) {
        const float* g = gi + (size_t)p * B_ * H3_ + (size_t)b * gi_stride;
        gr += g[j]; gz += g[H_ + j]; gn += g[2 * H_ + j];
    }
    if (PRE) {
        const float* g = gpre + (size_t)b * H3_;
        gr += g[j]; gz += g[H_ + j]; gn += g[2 * H_ + j];
    }
    if (bias_i) { gr += bias_i[j]; gz += bias_i[H_ + j]; gn += bias_i[2 * H_ + j]; }

    float hr = 0.f, hz = 0.f, hn = 0.f;
#pragma unroll
    for (int p = 0; p < GHP; p++) {
        const float* g = gh + (size_t)p * B_ * H3_ + (size_t)b * H3_;
        hr += g[j]; hz += g[H_ + j]; hn += g[2 * H_ + j];
    }
    hr += bias_h[j]; hz += bias_h[H_ + j]; hn += bias_h[2 * H_ + j];

    float r = 1.f / (1.f + expf(-(gr + hr)));
    float z = 1.f / (1.f + expf(-(gz + hz)));
    float n = tanhf(gn + r * hn);
    float h = (1.f - z) * n + z * hprev[idx];
    hout[idx] = h;
    if (extra) extra[(size_t)b * extra_stride + j] = h;
}

// ---------------- fused attention: scores + softmax + context ----------------
__global__ __launch_bounds__(256)
void k_attn(const float* __restrict__ d1, const int* __restrict__ src_ids,
            float* __restrict__ xctx, float* __restrict__ catctx)
{
    int b = blockIdx.x, tid = threadIdx.x;
    int warp = tid >> 5, lane = tid & 31;
    __shared__ float hc[H_];
    __shared__ float ev[S_];
    for (int i = tid; i < H_; i += 256) hc[i] = d1[b * H_ + i];
    __syncthreads();

#pragma unroll
    for (int si = 0; si < 8; si++) {
        int s = warp * 8 + si;
        const float* pr = g_proj + ((size_t)b * S_ + s) * H_;
        float acc = 0.f;
#pragma unroll 4
        for (int k = lane; k < H_; k += 32) acc += pr[k] * hc[k];
#pragma unroll
        for (int o = 16; o; o >>= 1) acc += __shfl_xor_sync(0xffffffffu, acc, o);
        if (lane == 0)
            ev[s] = (src_ids[b * S_ + s] != 0) ? acc : -1e9f;
    }
    __syncthreads();

    float mx = -1e30f;
#pragma unroll
    for (int s = 0; s < S_; s++) mx = fmaxf(mx, ev[s]);
    __syncthreads();
    if (tid < S_) ev[tid] = expf(ev[tid] - mx);
    __syncthreads();
    float sum = 0.f;
#pragma unroll
    for (int s = 0; s < S_; s++) sum += ev[s];
    float inv = 1.f / sum;

    for (int h = tid; h < H_; h += 256) {
        float acc = 0.f;
#pragma unroll
        for (int s = 0; s < S_; s++)
            acc += ev[s] * g_enc[((size_t)b * S_ + s) * H_ + h];
        acc *= inv;
        xctx[b * H_ + h] = acc;
        catctx[(size_t)b * 2 * H_ + h] = acc;
    }
}

// ---------------- host ----------------
extern "C" void kernel_launch(void* const* d_in, const int* in_sizes, int n_in,
                              void* d_out, int out_size)
{
    const int*   src_ids  = (const int*)d_in[0];
    const int*   tgt_ids  = (const int*)d_in[2];
    const float* enc_emb  = (const float*)d_in[3];
    const float* dec_emb  = (const float*)d_in[4];
    const float* enc_wih0 = (const float*)d_in[5];
    const float* enc_whh0 = (const float*)d_in[6];
    const float* enc_bih0 = (const float*)d_in[7];
    const float* enc_bhh0 = (const float*)d_in[8];
    const float* enc_wih1 = (const float*)d_in[9];
    const float* enc_whh1 = (const float*)d_in[10];
    const float* enc_bih1 = (const float*)d_in[11];
    const float* enc_bhh1 = (const float*)d_in[12];
    const float* dec_wih0 = (const float*)d_in[13];
    const float* dec_whh0 = (const float*)d_in[14];
    const float* dec_bih0 = (const float*)d_in[15];
    const float* dec_bhh0 = (const float*)d_in[16];
    const float* dec_wih1 = (const float*)d_in[17];
    const float* dec_whh1 = (const float*)d_in[18];
    const float* dec_bih1 = (const float*)d_in[19];
    const float* dec_bhh1 = (const float*)d_in[20];
    const float* attn_w   = (const float*)d_in[21];
    const float* out_w    = (const float*)d_in[22];
    const float* out_b    = (const float*)d_in[23];
    float* out = (float*)d_out;

    float *emb, *demb, *gi0, *giemb, *enc, *proj, *h0, *h1, *gip, *ghp, *x, *cat;
    cudaGetSymbolAddress((void**)&emb,   g_emb);
    cudaGetSymbolAddress((void**)&demb,  g_demb);
    cudaGetSymbolAddress((void**)&gi0,   g_gi0);
    cudaGetSymbolAddress((void**)&giemb, g_giemb);
    cudaGetSymbolAddress((void**)&enc,   g_enc);
    cudaGetSymbolAddress((void**)&proj,  g_proj);
    cudaGetSymbolAddress((void**)&h0,    g_h0);
    cudaGetSymbolAddress((void**)&h1,    g_h1);
    cudaGetSymbolAddress((void**)&gip,   g_gip);
    cudaGetSymbolAddress((void**)&ghp,   g_ghp);
    cudaGetSymbolAddress((void**)&x,     g_x);
    cudaGetSymbolAddress((void**)&cat,   g_cat);

    // 1) gathers + zero hidden
    k_init<<<(B_*S_*E_ + 255) / 256, 256>>>(src_ids, enc_emb);
    k_demb<<<(TD*B_*E_ + 255) / 256, 256>>>(tgt_ids, dec_emb);

    // 2) batched input-gate GEMMs
    k_gemm128<<<dim3(H3_/128, (B_*S_)/128), 256>>>(
        emb, enc_wih0, E_, enc_bih0, gi0, B_*S_, H3_, E_);
    k_gemm128<<<dim3(H3_/128, (TD*B_ + 127)/128), 256>>>(
        demb, dec_wih0, E_ + H_, dec_bih0, giemb, TD*B_, H3_, E_);

    // 3) encoder recurrence
    for (int t = 0; t < S_; t++) {
        k_gemm_small<<<dim3(H3_/64, KSPLIT, 1), 256>>>(
            h0, enc_whh0, H_, ghp, H_, nullptr, nullptr, 0, nullptr, 0, H3_);
        k_combine_t<1, KSPLIT, false><<<128, 256>>>(
            gi0 + (size_t)t * H3_, S_ * H3_, nullptr, nullptr,
            ghp, enc_bhh0, h0, h0, nullptr, 0);
        k_gemm_small<<<dim3(H3_/64, KSPLIT, 2), 256>>>(
            h0, enc_wih1, H_, gip, H_, h1, enc_whh1, H_, ghp, H_, H3_);
        k_combine_t<KSPLIT, KSPLIT, false><<<128, 256>>>(
            gip, H3_, enc_bih1, nullptr,
            ghp, enc_bhh1, h1, h1, enc + (size_t)t * H_, S_ * H_);
    }

    // 4) attention projection
    k_gemm128<<<dim3(H_/128, (B_*S_)/128), 256>>>(
        enc, attn_w, H_, nullptr, proj, B_*S_, H_, H_);

    // 5) decoder recurrence (logits deferred)
    for (int t = 0; t < TD; t++) {
        k_attn<<<B_, 256>>>(h1, src_ids, x, cat + (size_t)t*B_*2*H_ + H_);
        k_gemm_small<<<dim3(H3_/64, KSPLIT, 2), 256>>>(
            x, dec_wih0 + E_, E_ + H_, gip, H_,
            h0, dec_whh0, H_, ghp, H_, H3_);
        k_combine_t<KSPLIT, KSPLIT, true><<<128, 256>>>(
            gip, H3_, nullptr, giemb + (size_t)t*B_*H3_,
            ghp, dec_bhh0, h0, h0, nullptr, 0);
        k_gemm_small<<<dim3(H3_/64, KSPLIT, 2), 256>>>(
            h0, dec_wih1, H_, gip, H_, h1, dec_whh1, H_, ghp, H_, H3_);
        k_combine_t<KSPLIT, KSPLIT, false><<<128, 256>>>(
            gip, H3_, dec_bih1, nullptr,
            ghp, dec_bhh1, h1, h1, cat + (size_t)t*B_*2*H_, 2*H_);
    }

    // 6) tf32 tensor-core output projection, scattered to (B,TD,V)
    k_gemm_tc<<<dim3((TD*B_ + 127)/128, V_/128), 256>>>(
        cat, out_w, out_b, out, TD*B_, V_, 2*H_);
}

// round 4
// speedup vs baseline: 1.8132x; 1.3673x over previous
#include <cuda_runtime.h>
#include <math.h>
#include <stdint.h>

#define B_   32
#define S_   64
#define T_   48
#define TD   47
#define V_   32000
#define E_   512
#define H_   1024
#define H3_  3072
#define NBLK 128

// ---------------- device scratch ----------------
__device__ float g_emb  [B_*S_*E_];
__device__ float g_demb [TD*B_*E_];
__device__ float g_gi0  [B_*S_*H3_];
__device__ float g_giemb[TD*B_*H3_];
__device__ float g_enc  [B_*S_*H_];
__device__ float g_proj [B_*S_*H_];
__device__ float g_h0   [2][B_*H_];
__device__ float g_h1   [2][B_*H_];
__device__ float g_score[B_*S_];
__device__ float g_x    [B_*H_];
__device__ float g_cat  [TD*B_*2*H_];
__device__ unsigned g_count;

__global__ void k_reset() { g_count = 0u; }

// ---------------- gathers ----------------
__global__ void k_init(const int* __restrict__ src_ids, const float* __restrict__ enc_emb)
{
    int idx = blockIdx.x * blockDim.x + threadIdx.x;
    if (idx < B_*S_*E_) {
        int m = idx >> 9, k = idx & 511;
        g_emb[idx] = enc_emb[(size_t)src_ids[m] * E_ + k];
    }
}
__global__ void k_demb(const int* __restrict__ tgt_ids, const float* __restrict__ dec_emb)
{
    int idx = blockIdx.x * blockDim.x + threadIdx.x;
    if (idx >= TD*B_*E_) return;
    int m = idx >> 9, k = idx & 511;
    int b = m & 31, t = m >> 5;
    g_demb[idx] = dec_emb[(size_t)tgt_ids[b*T_ + t] * E_ + k];
}

// ---------------- tf32 mma helpers ----------------
__device__ __forceinline__ uint32_t f2tf32(float f) {
    uint32_t u; asm("cvt.rna.tf32.f32 %0, %1;" : "=r"(u) : "f"(f)); return u;
}
__device__ __forceinline__ void mma_tf32(float c[4], const uint32_t a[4], const uint32_t b[2]) {
    asm volatile(
        "mma.sync.aligned.m16n8k8.row.col.f32.tf32.tf32.f32 "
        "{%0,%1,%2,%3}, {%4,%5,%6,%7}, {%8,%9}, {%0,%1,%2,%3};\n"
        : "+f"(c[0]), "+f"(c[1]), "+f"(c[2]), "+f"(c[3])
        : "r"(a[0]), "r"(a[1]), "r"(a[2]), "r"(a[3]), "r"(b[0]), "r"(b[1]));
}

// ---------------- grid barrier (monotonic counter; reset per replay) ----------------
__device__ __forceinline__ void gbar(unsigned &target) {
    __threadfence();
    __syncthreads();
    if (threadIdx.x == 0) {
        atomicAdd(&g_count, 1u);
        target += NBLK;
        while (*(volatile unsigned*)&g_count < target) { }
    }
    __syncthreads();
}

// ---------------- per-block GEMV pass: acc += A[32xK=1024] @ Wrows^T (3 gate groups of 8) ----
// warp w handles k in [w*128, w*128+128).  A read via ldcg (cross-block state).
__device__ __forceinline__ void gemv_pass(float acc[2][3][4],
        const float* __restrict__ A, int lda,
        const float* __restrict__ W, int ldw,
        int jt0, int lane, int warp)
{
    int g = lane >> 2, tg = lane & 3;
    int kbeg = warp * 128;
    const float* w0 = W + (size_t)(jt0 + g) * ldw;
    const float* w1 = W + (size_t)(H_ + jt0 + g) * ldw;
    const float* w2 = W + (size_t)(2*H_ + jt0 + g) * ldw;
#pragma unroll 4
    for (int kk = kbeg; kk < kbeg + 128; kk += 8) {
        uint32_t af[2][4];
#pragma unroll
        for (int mt = 0; mt < 2; mt++) {
            const float* ap = A + (size_t)(mt*16 + g) * lda + kk;
            af[mt][0] = f2tf32(__ldcg(ap + tg));
            af[mt][1] = f2tf32(__ldcg(ap + 8*lda + tg));
            af[mt][2] = f2tf32(__ldcg(ap + tg + 4));
            af[mt][3] = f2tf32(__ldcg(ap + 8*lda + tg + 4));
        }
        uint32_t bf[2];
        bf[0] = f2tf32(__ldg(w0 + kk + tg));
        bf[1] = f2tf32(__ldg(w0 + kk + tg + 4));
        mma_tf32(acc[0][0], af[0], bf);
        mma_tf32(acc[1][0], af[1], bf);
        bf[0] = f2tf32(__ldg(w1 + kk + tg));
        bf[1] = f2tf32(__ldg(w1 + kk + tg + 4));
        mma_tf32(acc[0][1], af[0], bf);
        mma_tf32(acc[1][1], af[1], bf);
        bf[0] = f2tf32(__ldg(w2 + kk + tg));
        bf[1] = f2tf32(__ldg(w2 + kk + tg + 4));
        mma_tf32(acc[0][2], af[0], bf);
        mma_tf32(acc[1][2], af[1], bf);
    }
}

// reduce 8 warps' partial C[32x24] frags -> s_out[768] (row*24+col)
__device__ __forceinline__ void reduce_acc(const float acc[2][3][4],
        float* s_red, float* s_out, int lane, int warp)
{
    int g = lane >> 2, tg = lane & 3;
#pragma unroll
    for (int mt = 0; mt < 2; mt++)
#pragma unroll
    for (int nt = 0; nt < 3; nt++)
#pragma unroll
    for (int q = 0; q < 4; q++) {
        int row = mt*16 + g + ((q >> 1) << 3);
        int col = nt*8 + 2*tg + (q & 1);
        s_red[warp*768 + row*24 + col] = acc[mt][nt][q];
    }
    __syncthreads();
    int tid = threadIdx.x;
    for (int e = tid; e < 768; e += 256) {
        float s = 0.f;
#pragma unroll
        for (int w = 0; w < 8; w++) s += s_red[w*768 + e];
        s_out[e] = s;
    }
    __syncthreads();
}

__device__ __forceinline__ float sigf(float x) { return 1.f / (1.f + expf(-x)); }

// ---------------- persistent encoder ----------------
__global__ void __launch_bounds__(256) k_enc(
    const float* __restrict__ whh0, const float* __restrict__ wih1,
    const float* __restrict__ whh1,
    const float* __restrict__ bhh0, const float* __restrict__ bih1,
    const float* __restrict__ bhh1)
{
    __shared__ float s_red[8*768];
    __shared__ float s_gi[768];
    __shared__ float s_gh[768];
    int tid = threadIdx.x, lane = tid & 31, warp = tid >> 5;
    int jt0 = blockIdx.x * 8;
    int cb = tid >> 3, cj = tid & 7;
    unsigned target = 0;

    int gidx = blockIdx.x * 256 + tid;     // 128*256 = B_*H_
    g_h0[0][gidx] = 0.f;
    g_h1[0][gidx] = 0.f;
    gbar(target);

    for (int t = 0; t < S_; t++) {
        int p = t & 1;
        // ---- layer0: gh = whh0 @ h0[p]
        float ah[2][3][4] = {};
        gemv_pass(ah, g_h0[p], H_, whh0, H_, jt0, lane, warp);
        reduce_acc(ah, s_red, s_gh, lane, warp);
        {
            int j = jt0 + cj;
            const float* gi = g_gi0 + ((size_t)cb * S_ + t) * H3_;
            float gir = gi[j], giz = gi[H_ + j], gin = gi[2*H_ + j];
            float ghr = s_gh[cb*24 + cj]      + bhh0[j];
            float ghz = s_gh[cb*24 + 8 + cj]  + bhh0[H_ + j];
            float ghn = s_gh[cb*24 + 16 + cj] + bhh0[2*H_ + j];
            float hp  = __ldcg(&g_h0[p][cb*H_ + j]);
            float r = sigf(gir + ghr);
            float z = sigf(giz + ghz);
            float n = tanhf(gin + r * ghn);
            g_h0[1-p][cb*H_ + j] = (1.f - z) * n + z * hp;
        }
        gbar(target);
        // ---- layer1: gi = wih1 @ h0[1-p], gh = whh1 @ h1[p]
        float ai[2][3][4] = {};
        float ah2[2][3][4] = {};
        gemv_pass(ai,  g_h0[1-p], H_, wih1, H_, jt0, lane, warp);
        gemv_pass(ah2, g_h1[p],   H_, whh1, H_, jt0, lane, warp);
        reduce_acc(ai,  s_red, s_gi, lane, warp);
        reduce_acc(ah2, s_red, s_gh, lane, warp);
        {
            int j = jt0 + cj;
            float gir = s_gi[cb*24 + cj]      + bih1[j];
            float giz = s_gi[cb*24 + 8 + cj]  + bih1[H_ + j];
            float gin = s_gi[cb*24 + 16 + cj] + bih1[2*H_ + j];
            float ghr = s_gh[cb*24 + cj]      + bhh1[j];
            float ghz = s_gh[cb*24 + 8 + cj]  + bhh1[H_ + j];
            float ghn = s_gh[cb*24 + 16 + cj] + bhh1[2*H_ + j];
            float hp  = __ldcg(&g_h1[p][cb*H_ + j]);
            float r = sigf(gir + ghr);
            float z = sigf(giz + ghz);
            float n = tanhf(gin + r * ghn);
            float hnew = (1.f - z) * n + z * hp;
            g_h1[1-p][cb*H_ + j] = hnew;
            g_enc[((size_t)cb * S_ + t) * H_ + j] = hnew;
        }
        gbar(target);
    }
}

// ---------------- persistent decoder ----------------
__global__ void __launch_bounds__(256) k_dec(
    const int* __restrict__ src_ids,
    const float* __restrict__ whh0, const float* __restrict__ wih0c,  // wih0c = dec_wih0+512, ldw 1536
    const float* __restrict__ wih1, const float* __restrict__ whh1,
    const float* __restrict__ bhh0, const float* __restrict__ bih1,
    const float* __restrict__ bhh1)
{
    __shared__ float s_red[8*768];
    __shared__ float s_gi[768];
    __shared__ float s_gh[768];
    __shared__ float s_sc[S_];
    __shared__ float s_ev[S_];
    __shared__ float s_mx, s_inv;
    int tid = threadIdx.x, lane = tid & 31, warp = tid >> 5;
    int jt0 = blockIdx.x * 8;
    int cb = tid >> 3, cj = tid & 7;
    int ab = blockIdx.x >> 2;                 // attn ctx batch
    int ah0 = (blockIdx.x & 3) * 256;         // attn ctx h-slice
    unsigned target = 0;

    for (int t = 0; t < TD; t++) {
        int p = t & 1;
        const float* d1p = g_h1[p];
        // ---- P1: scores
        {
            int gw = blockIdx.x * 8 + warp;
#pragma unroll
            for (int dd = 0; dd < 2; dd++) {
                int d = gw * 2 + dd;
                int b = d >> 6, s = d & 63;
                const float* pr = g_proj + ((size_t)b * S_ + s) * H_;
                const float* hv = d1p + b * H_;
                float acc = 0.f;
#pragma unroll 8
                for (int k = lane; k < H_; k += 32)
                    acc += __ldg(pr + k) * __ldcg(hv + k);
#pragma unroll
                for (int o = 16; o; o >>= 1) acc += __shfl_xor_sync(0xffffffffu, acc, o);
                if (lane == 0)
                    g_score[d] = (src_ids[b*S_ + s] != 0) ? acc : -1e9f;
            }
        }
        gbar(target);
        // ---- P2: softmax + ctx
        {
            if (tid < S_) s_sc[tid] = __ldcg(&g_score[ab*S_ + tid]);
            __syncthreads();
            if (tid == 0) {
                float mx = -1e30f;
#pragma unroll
                for (int s = 0; s < S_; s++) mx = fmaxf(mx, s_sc[s]);
                s_mx = mx;
            }
            __syncthreads();
            if (tid < S_) s_ev[tid] = expf(s_sc[tid] - s_mx);
            __syncthreads();
            if (tid == 0) {
                float su = 0.f;
#pragma unroll
                for (int s = 0; s < S_; s++) su += s_ev[s];
                s_inv = 1.f / su;
            }
            __syncthreads();
            int h = ah0 + tid;
            const float* ep = g_enc + (size_t)ab * S_ * H_ + h;
            float acc = 0.f;
#pragma unroll 8
            for (int s = 0; s < S_; s++)
                acc += s_ev[s] * __ldg(ep + (size_t)s * H_);
            acc *= s_inv;
            g_x[ab*H_ + h] = acc;
            g_cat[((size_t)t * B_ + ab) * (2*H_) + H_ + h] = acc;
        }
        gbar(target);
        // ---- P3: layer0  gi = wih0c@ctx (+giemb), gh = whh0@d0[p]
        {
            float ai[2][3][4] = {};
            float ahh[2][3][4] = {};
            gemv_pass(ai,  g_x,      H_, wih0c, E_ + H_, jt0, lane, warp);
            gemv_pass(ahh, g_h0[p],  H_, whh0,  H_,      jt0, lane, warp);
            reduce_acc(ai,  s_red, s_gi, lane, warp);
            reduce_acc(ahh, s_red, s_gh, lane, warp);
            int j = jt0 + cj;
            const float* ge = g_giemb + ((size_t)t * B_ + cb) * H3_;
            float gir = s_gi[cb*24 + cj]      + ge[j];
            float giz = s_gi[cb*24 + 8 + cj]  + ge[H_ + j];
            float gin = s_gi[cb*24 + 16 + cj] + ge[2*H_ + j];
            float ghr = s_gh[cb*24 + cj]      + bhh0[j];
            float ghz = s_gh[cb*24 + 8 + cj]  + bhh0[H_ + j];
            float ghn = s_gh[cb*24 + 16 + cj] + bhh0[2*H_ + j];
            float hp  = __ldcg(&g_h0[p][cb*H_ + j]);
            float r = sigf(gir + ghr);
            float z = sigf(giz + ghz);
            float n = tanhf(gin + r * ghn);
            g_h0[1-p][cb*H_ + j] = (1.f - z) * n + z * hp;
        }
        gbar(target);
        // ---- P4: layer1
        {
            float ai[2][3][4] = {};
            float ahh[2][3][4] = {};
            gemv_pass(ai,  g_h0[1-p], H_, wih1, H_, jt0, lane, warp);
            gemv_pass(ahh, g_h1[p],   H_, whh1, H_, jt0, lane, warp);
            reduce_acc(ai,  s_red, s_gi, lane, warp);
            reduce_acc(ahh, s_red, s_gh, lane, warp);
            int j = jt0 + cj;
            float gir = s_gi[cb*24 + cj]      + bih1[j];
            float giz = s_gi[cb*24 + 8 + cj]  + bih1[H_ + j];
            float gin = s_gi[cb*24 + 16 + cj] + bih1[2*H_ + j];
            float ghr = s_gh[cb*24 + cj]      + bhh1[j];
            float ghz = s_gh[cb*24 + 8 + cj]  + bhh1[H_ + j];
            float ghn = s_gh[cb*24 + 16 + cj] + bhh1[2*H_ + j];
            float hp  = __ldcg(&g_h1[p][cb*H_ + j]);
            float r = sigf(gir + ghr);
            float z = sigf(giz + ghz);
            float n = tanhf(gin + r * ghn);
            float hnew = (1.f - z) * n + z * hp;
            g_h1[1-p][cb*H_ + j] = hnew;
            g_cat[((size_t)t * B_ + cb) * (2*H_) + j] = hnew;
        }
        gbar(target);
    }
}

// ---------------- tf32 tensor-core GEMM (batch + output) ----------------
// mode 0: C[m*N+n]   mode 1: scatter out (B,TD,V) with m = t*B+b
__global__ __launch_bounds__(256, 2)
void k_gemm_tc(const float* __restrict__ A, int lda,
               const float* __restrict__ W, int ldw,
               const float* __restrict__ bias, float* __restrict__ C,
               int M, int N, int K, int mode)
{
    __shared__ float As[2][128*20];
    __shared__ float Bs[2][128*20];
    const int tid = threadIdx.x;
    const int m0 = blockIdx.x * 128;
    const int n0 = blockIdx.y * 128;
    const int warp = tid >> 5, lane = tid & 31;
    const int g = lane >> 2, tg = lane & 3;
    const int wm = (warp >> 2) * 64, wn = (warp & 3) * 32;

    const int lrow = tid >> 2;
    const int lk   = (tid & 3) * 4;
    int ar0 = m0 + lrow;      if (ar0 >= M) ar0 = M - 1;
    int ar1 = m0 + lrow + 64; if (ar1 >= M) ar1 = M - 1;
    const float* ag0 = A + (size_t)ar0 * lda + lk;
    const float* ag1 = A + (size_t)ar1 * lda + lk;
    const float* bg0 = W + (size_t)(n0 + lrow) * ldw + lk;
    const float* bg1 = W + (size_t)(n0 + lrow + 64) * ldw + lk;
    uint32_t sa0 = (uint32_t)__cvta_generic_to_shared(&As[0][lrow*20 + lk]);
    uint32_t sa1 = (uint32_t)__cvta_generic_to_shared(&As[0][(lrow+64)*20 + lk]);
    uint32_t sb0 = (uint32_t)__cvta_generic_to_shared(&Bs[0][lrow*20 + lk]);
    uint32_t sb1 = (uint32_t)__cvta_generic_to_shared(&Bs[0][(lrow+64)*20 + lk]);
    const uint32_t ssz = 128*20*4;

    float acc[4][4][4];
#pragma unroll
    for (int i = 0; i < 4; i++)
#pragma unroll
        for (int j = 0; j < 4; j++)
#pragma unroll
            for (int q = 0; q < 4; q++) acc[i][j][q] = 0.f;

    auto issue = [&](int st, int c) {
        uint32_t so = st ? ssz : 0;
        const float* p0 = ag0 + c*16;
        const float* p1 = ag1 + c*16;
        const float* p2 = bg0 + c*16;
        const float* p3 = bg1 + c*16;
        asm volatile("cp.async.cg.shared.global [%0], [%1], 16;\n" :: "r"(sa0+so), "l"(p0));
        asm volatile("cp.async.cg.shared.global [%0], [%1], 16;\n" :: "r"(sa1+so), "l"(p1));
        asm volatile("cp.async.cg.shared.global [%0], [%1], 16;\n" :: "r"(sb0+so), "l"(p2));
        asm volatile("cp.async.cg.shared.global [%0], [%1], 16;\n" :: "r"(sb1+so), "l"(p3));
    };

    const int nchunk = K / 16;
    issue(0, 0);
    asm volatile("cp.async.commit_group;\n");

    for (int c = 0; c < nchunk; c++) {
        if (c + 1 < nchunk) issue((c + 1) & 1, c + 1);
        asm volatile("cp.async.commit_group;\n");
        asm volatile("cp.async.wait_group 1;\n");
        __syncthreads();
        const float* as = As[c & 1];
        const float* bs = Bs[c & 1];
#pragma unroll
        for (int ks = 0; ks < 16; ks += 8) {
            uint32_t af[4][4], bf[4][2];
#pragma unroll
            for (int i = 0; i < 4; i++) {
                int r = wm + i*16 + g;
                af[i][0] = f2tf32(as[r*20 + ks + tg]);
                af[i][1] = f2tf32(as[(r+8)*20 + ks + tg]);
                af[i][2] = f2tf32(as[r*20 + ks + tg + 4]);
                af[i][3] = f2tf32(as[(r+8)*20 + ks + tg + 4]);
            }
#pragma unroll
            for (int j = 0; j < 4; j++) {
                int cc = wn + j*8 + g;
                bf[j][0] = f2tf32(bs[cc*20 + ks + tg]);
                bf[j][1] = f2tf32(bs[cc*20 + ks + tg + 4]);
            }
#pragma unroll
            for (int i = 0; i < 4; i++)
#pragma unroll
                for (int j = 0; j < 4; j++)
                    mma_tf32(acc[i][j], af[i], bf[j]);
        }
        __syncthreads();
    }

#pragma unroll
    for (int i = 0; i < 4; i++) {
#pragma unroll
        for (int j = 0; j < 4; j++) {
            int n = n0 + wn + j*8 + 2*tg;
            float bv0 = bias ? bias[n] : 0.f;
            float bv1 = bias ? bias[n + 1] : 0.f;
            int m = m0 + wm + i*16 + g;
            if (m < M) {
                float* o;
                if (mode == 0) o = C + (size_t)m * N + n;
                else {
                    int bb = m & (B_ - 1), tt = m >> 5;
                    o = C + (size_t)bb*TD*V_ + (size_t)tt*V_ + n;
                }
                o[0] = acc[i][j][0] + bv0;
                o[1] = acc[i][j][1] + bv1;
            }
            int m2 = m + 8;
            if (m2 < M) {
                float* o;
                if (mode == 0) o = C + (size_t)m2 * N + n;
                else {
                    int bb = m2 & (B_ - 1), tt = m2 >> 5;
                    o = C + (size_t)bb*TD*V_ + (size_t)tt*V_ + n;
                }
                o[0] = acc[i][j][2] + bv0;
                o[1] = acc[i][j][3] + bv1;
            }
        }
    }
}

// ---------------- host ----------------
extern "C" void kernel_launch(void* const* d_in, const int* in_sizes, int n_in,
                              void* d_out, int out_size)
{
    const int*   src_ids  = (const int*)d_in[0];
    const int*   tgt_ids  = (const int*)d_in[2];
    const float* enc_emb  = (const float*)d_in[3];
    const float* dec_emb  = (const float*)d_in[4];
    const float* enc_wih0 = (const float*)d_in[5];
    const float* enc_whh0 = (const float*)d_in[6];
    const float* enc_bih0 = (const float*)d_in[7];
    const float* enc_bhh0 = (const float*)d_in[8];
    const float* enc_wih1 = (const float*)d_in[9];
    const float* enc_whh1 = (const float*)d_in[10];
    const float* enc_bih1 = (const float*)d_in[11];
    const float* enc_bhh1 = (const float*)d_in[12];
    const float* dec_wih0 = (const float*)d_in[13];
    const float* dec_whh0 = (const float*)d_in[14];
    const float* dec_bih0 = (const float*)d_in[15];
    const float* dec_bhh0 = (const float*)d_in[16];
    const float* dec_wih1 = (const float*)d_in[17];
    const float* dec_whh1 = (const float*)d_in[18];
    const float* dec_bih1 = (const float*)d_in[19];
    const float* dec_bhh1 = (const float*)d_in[20];
    const float* attn_w   = (const float*)d_in[21];
    const float* out_w    = (const float*)d_in[22];
    const float* out_b    = (const float*)d_in[23];
    float* out = (float*)d_out;

    float *emb, *demb, *gi0, *giemb, *enc, *proj, *cat;
    cudaGetSymbolAddress((void**)&emb,   g_emb);
    cudaGetSymbolAddress((void**)&demb,  g_demb);
    cudaGetSymbolAddress((void**)&gi0,   g_gi0);
    cudaGetSymbolAddress((void**)&giemb, g_giemb);
    cudaGetSymbolAddress((void**)&enc,   g_enc);
    cudaGetSymbolAddress((void**)&proj,  g_proj);
    cudaGetSymbolAddress((void**)&cat,   g_cat);

    // gathers
    k_init<<<(B_*S_*E_ + 255)/256, 256>>>(src_ids, enc_emb);
    k_demb<<<(TD*B_*E_ + 255)/256, 256>>>(tgt_ids, dec_emb);

    // batched input-gate GEMMs (tf32)
    k_gemm_tc<<<dim3((B_*S_)/128, H3_/128), 256>>>(
        emb, E_, enc_wih0, E_, enc_bih0, gi0, B_*S_, H3_, E_, 0);
    k_gemm_tc<<<dim3((TD*B_ + 127)/128, H3_/128), 256>>>(
        demb, E_, dec_wih0, E_ + H_, dec_bih0, giemb, TD*B_, H3_, E_, 0);

    // persistent encoder
    k_reset<<<1, 1>>>();
    k_enc<<<NBLK, 256>>>(enc_whh0, enc_wih1, enc_whh1,
                         enc_bhh0, enc_bih1, enc_bhh1);

    // attention projection (tf32)
    k_gemm_tc<<<dim3((B_*S_)/128, H_/128), 256>>>(
        enc, H_, attn_w, H_, nullptr, proj, B_*S_, H_, H_, 0);

    // persistent decoder
    k_reset<<<1, 1>>>();
    k_dec<<<NBLK, 256>>>(src_ids, dec_whh0, dec_wih0 + E_,
                         dec_wih1, dec_whh1,
                         dec_bhh0, dec_bih1, dec_bhh1);

    // output projection (tf32, scatter)
    k_gemm_tc<<<dim3((TD*B_ + 127)/128, V_/128), 256>>>(
        cat, 2*H_, out_w, 2*H_, out_b, out, TD*B_, V_, 2*H_, 1);
}